// round 1
// baseline (speedup 1.0000x reference)
#include <cuda_runtime.h>
#include <math.h>

#define DMODEL 2048
#define NHEADS 16
#define DHEAD  128
#define SEQ    2048
#define BATCH  2
#define BHN    (BATCH*NHEADS)   // 32
#define MROWS  (BATCH*SEQ)      // 4096

// log2(e) / sqrt(128): folds softmax base-2 conversion and attention scale into q.
#define QSCALE (1.4426950408889634f * 0.08838834764831845f)

#define GEMM_SMEM  ((32*128 + 32*256) * 4)                       // 49152 B
#define FLASH_SMEM ((128*64 + 128*64 + 64*128 + 64*68) * 4)      // 115712 B

// Scratch (device globals: allocation-free per harness rules)
__device__ float  g_q[(size_t)BHN * SEQ * DHEAD];   // [b][h][p][e]
__device__ float  g_k[(size_t)BHN * SEQ * DHEAD];
__device__ float  g_v[(size_t)BHN * SEQ * DHEAD];
__device__ float  g_z[(size_t)MROWS * DMODEL];      // [b*p][h*e] row-major
__device__ float2 g_rope[SEQ * 64];                 // (sin, cos)

__device__ __forceinline__ void fma2(unsigned long long& d,
                                     unsigned long long a,
                                     unsigned long long b) {
    asm("fma.rn.f32x2 %0, %1, %2, %0;" : "+l"(d) : "l"(a), "l"(b));
}

// ---------------------------------------------------------------------------
// RoPE sin/cos table. fp32 angle (matches reference rounding), fp64 sin/cos.
// ---------------------------------------------------------------------------
__global__ void rope_table_kernel() {
    int p = blockIdx.x;
    int i = threadIdx.x;  // 0..63
    float freq = (float)pow(10000.0, (double)i / 64.0);
    float ang  = (float)p / freq;
    double s, c;
    sincos((double)ang, &s, &c);
    g_rope[p * 64 + i] = make_float2((float)s, (float)c);
}

// ---------------------------------------------------------------------------
// Apply rotary to q (with QSCALE folded) and k, in place.
// ---------------------------------------------------------------------------
__global__ void rope_kernel() {
    int gid = blockIdx.x * 256 + threadIdx.x;
    int i    = gid & 63;
    int rest = gid >> 6;
    int p    = rest & 2047;
    int bh   = rest >> 11;
    float2 sc = g_rope[p * 64 + i];
    size_t base = ((size_t)bh * SEQ + p) * DHEAD;

    float x0 = g_q[base + i], x1 = g_q[base + 64 + i];
    g_q[base + i]      = (x0 * sc.y - x1 * sc.x) * QSCALE;
    g_q[base + 64 + i] = (x1 * sc.y + x0 * sc.x) * QSCALE;

    float y0 = g_k[base + i], y1 = g_k[base + 64 + i];
    g_k[base + i]      = y0 * sc.y - y1 * sc.x;
    g_k[base + 64 + i] = y1 * sc.y + y0 * sc.x;
}

// ---------------------------------------------------------------------------
// fp32 GEMM, 128x128x32 tiles, 256 threads, 8x8 micro-tile via fma.rn.f32x2.
// B is stored duplicated in smem ((b,b) pairs) so the inner loop has zero
// packing ALU: A pairs are m-contiguous, B pairs are pre-duplicated.
// mode 0: QKV projection  (W layout [h][d][e], wstride=128, out -> [b][h][p][e])
// mode 1: O projection    (W layout [k][n],    wstride=2048, out -> row-major)
// ---------------------------------------------------------------------------
__global__ __launch_bounds__(256, 2) void gemm_kernel(
    const float* __restrict__ A,
    const float* __restrict__ Wg,
    int wstride,
    const float* __restrict__ bias,
    float* __restrict__ out,
    int mode)
{
    extern __shared__ float gsm[];
    float* As = gsm;            // [32][128], transposed A tile
    float* Bs = gsm + 32 * 128; // [32][256], duplicated B tile

    const int tid  = threadIdx.x;
    const int bx   = blockIdx.x;
    const int row0 = blockIdx.y * 128;
    const int tx   = tid & 15;
    const int ty   = tid >> 4;

    const float* Wb = (mode == 0) ? (Wg + (size_t)bx * (DMODEL * DHEAD))
                                  : (Wg + bx * 128);

    unsigned long long acc[4][8];
#pragma unroll
    for (int i = 0; i < 4; ++i)
#pragma unroll
        for (int j = 0; j < 8; ++j) acc[i][j] = 0ULL;

    for (int kt = 0; kt < DMODEL / 32; ++kt) {
        const int d0 = kt * 32;
#pragma unroll
        for (int it = 0; it < 4; ++it) {
            int f  = tid + it * 256;         // 0..1023
            int m  = f >> 3;                 // 0..127
            int k0 = (f & 7) * 4;            // 0..28
            float4 v = *(const float4*)(A + (size_t)(row0 + m) * DMODEL + d0 + k0);
            As[(k0 + 0) * 128 + m] = v.x;
            As[(k0 + 1) * 128 + m] = v.y;
            As[(k0 + 2) * 128 + m] = v.z;
            As[(k0 + 3) * 128 + m] = v.w;
        }
#pragma unroll
        for (int it = 0; it < 4; ++it) {
            int f  = tid + it * 256;
            int k  = f >> 5;                 // 0..31
            int n0 = (f & 31) * 4;           // 0..124
            float4 v = *(const float4*)(Wb + (size_t)(d0 + k) * wstride + n0);
            float4 lo = make_float4(v.x, v.x, v.y, v.y);
            float4 hi = make_float4(v.z, v.z, v.w, v.w);
            *(float4*)&Bs[k * 256 + 2 * n0]     = lo;
            *(float4*)&Bs[k * 256 + 2 * n0 + 4] = hi;
        }
        __syncthreads();

#pragma unroll 8
        for (int k = 0; k < 32; ++k) {
            ulonglong2 a01 = *(const ulonglong2*)&As[k * 128 + tx * 8];
            ulonglong2 a23 = *(const ulonglong2*)&As[k * 128 + tx * 8 + 4];
            const ulonglong2* bp = (const ulonglong2*)&Bs[k * 256 + ty * 16];
            ulonglong2 b0 = bp[0], b1 = bp[1], b2 = bp[2], b3 = bp[3];
            unsigned long long av[4] = {a01.x, a01.y, a23.x, a23.y};
            unsigned long long bv[8] = {b0.x, b0.y, b1.x, b1.y, b2.x, b2.y, b3.x, b3.y};
#pragma unroll
            for (int mp = 0; mp < 4; ++mp)
#pragma unroll
                for (int n = 0; n < 8; ++n)
                    fma2(acc[mp][n], av[mp], bv[n]);
        }
        __syncthreads();
    }

    float bv8[8];
#pragma unroll
    for (int n = 0; n < 8; ++n) bv8[n] = bias[bx * 128 + ty * 8 + n];

#pragma unroll
    for (int mp = 0; mp < 4; ++mp) {
#pragma unroll
        for (int hf = 0; hf < 2; ++hf) {
            int m = row0 + tx * 8 + mp * 2 + hf;
            float vals[8];
#pragma unroll
            for (int n = 0; n < 8; ++n) {
                unsigned long long a = acc[mp][n];
                unsigned int u32 = hf ? (unsigned int)(a >> 32) : (unsigned int)a;
                vals[n] = __uint_as_float(u32) + bv8[n];
            }
            float4 v0 = make_float4(vals[0], vals[1], vals[2], vals[3]);
            float4 v1 = make_float4(vals[4], vals[5], vals[6], vals[7]);
            float* o;
            if (mode == 0) {
                int b = m >> 11, p = m & 2047;
                o = out + (((size_t)(b * NHEADS + bx) * SEQ + p) << 7) + ty * 8;
            } else {
                o = out + (size_t)m * DMODEL + bx * 128 + ty * 8;
            }
            *(float4*)o       = v0;
            *(float4*)(o + 4) = v1;
        }
    }
}

// ---------------------------------------------------------------------------
// Causal flash attention, fp32. BM=BN=64, dh=128, 256 threads (16x16).
// q already carries QSCALE (log2e / sqrt(128)); softmax in exp2 domain.
// Output -> g_z[b*p][h*e] (row-major for the O projection).
// ---------------------------------------------------------------------------
__global__ __launch_bounds__(256, 1) void flash_kernel() {
    extern __shared__ float sm[];
    float* Qt = sm;               // [128][64]  (d-major, transposed)
    float* Kt = sm + 128 * 64;    // [128][64]
    float* Vs = Kt + 128 * 64;    // [64][128]
    float* Ps = Vs + 64 * 128;    // [64][68]   (padded)

    const int tid = threadIdx.x;
    const int u = tid & 15;       // S col block / O col block
    const int w = tid >> 4;       // row block
    const int bh = blockIdx.y;
    const int q0 = blockIdx.x * 64;

    const float* qp = g_q + (size_t)bh * SEQ * DHEAD;
    const float* kp = g_k + (size_t)bh * SEQ * DHEAD;
    const float* vp = g_v + (size_t)bh * SEQ * DHEAD;

    // Load Q tile, transposed
#pragma unroll
    for (int it = 0; it < 8; ++it) {
        int f  = tid + it * 256;   // 0..2047
        int j  = f >> 5;           // 0..63
        int d0 = (f & 31) * 4;     // 0..124
        float4 v = *(const float4*)(qp + (size_t)(q0 + j) * DHEAD + d0);
        Qt[(d0 + 0) * 64 + j] = v.x;
        Qt[(d0 + 1) * 64 + j] = v.y;
        Qt[(d0 + 2) * 64 + j] = v.z;
        Qt[(d0 + 3) * 64 + j] = v.w;
    }

    float m_i[4], l_i[4], co[4][8];
#pragma unroll
    for (int r = 0; r < 4; ++r) {
        m_i[r] = -1e30f; l_i[r] = 0.0f;
#pragma unroll
        for (int c = 0; c < 8; ++c) co[r][c] = 0.0f;
    }

    const int ntiles = blockIdx.x + 1;
    for (int t = 0; t < ntiles; ++t) {
        const int k0 = t * 64;
        __syncthreads();
#pragma unroll
        for (int it = 0; it < 8; ++it) {
            int f  = tid + it * 256;
            int j  = f >> 5;
            int d0 = (f & 31) * 4;
            float4 kv = *(const float4*)(kp + (size_t)(k0 + j) * DHEAD + d0);
            Kt[(d0 + 0) * 64 + j] = kv.x;
            Kt[(d0 + 1) * 64 + j] = kv.y;
            Kt[(d0 + 2) * 64 + j] = kv.z;
            Kt[(d0 + 3) * 64 + j] = kv.w;
            float4 vv = *(const float4*)(vp + (size_t)(k0 + j) * DHEAD + d0);
            *(float4*)&Vs[j * 128 + d0] = vv;
        }
        __syncthreads();

        // S = Q K^T (scaled, log2 domain)
        float s[4][4];
#pragma unroll
        for (int r = 0; r < 4; ++r)
#pragma unroll
            for (int c = 0; c < 4; ++c) s[r][c] = 0.0f;

#pragma unroll 4
        for (int d = 0; d < 128; ++d) {
            float4 qv = *(const float4*)&Qt[d * 64 + w * 4];
            float4 kv = *(const float4*)&Kt[d * 64 + u * 4];
            float qa[4] = {qv.x, qv.y, qv.z, qv.w};
            float ka[4] = {kv.x, kv.y, kv.z, kv.w};
#pragma unroll
            for (int r = 0; r < 4; ++r)
#pragma unroll
                for (int c = 0; c < 4; ++c) s[r][c] += qa[r] * ka[c];
        }

        if (t == ntiles - 1) {  // diagonal tile: causal mask
#pragma unroll
            for (int r = 0; r < 4; ++r)
#pragma unroll
                for (int c = 0; c < 4; ++c)
                    if (k0 + u * 4 + c > q0 + w * 4 + r) s[r][c] = -1e30f;
        }

        // Online softmax (exp2 domain)
#pragma unroll
        for (int r = 0; r < 4; ++r) {
            float mx = fmaxf(fmaxf(s[r][0], s[r][1]), fmaxf(s[r][2], s[r][3]));
#pragma unroll
            for (int off = 8; off >= 1; off >>= 1)
                mx = fmaxf(mx, __shfl_xor_sync(0xffffffffu, mx, off));
            float mn = fmaxf(m_i[r], mx);
            float scale = exp2f(m_i[r] - mn);
            float rs = 0.0f;
#pragma unroll
            for (int c = 0; c < 4; ++c) { s[r][c] = exp2f(s[r][c] - mn); rs += s[r][c]; }
#pragma unroll
            for (int off = 8; off >= 1; off >>= 1)
                rs += __shfl_xor_sync(0xffffffffu, rs, off);
            l_i[r] = l_i[r] * scale + rs;
            m_i[r] = mn;
#pragma unroll
            for (int c = 0; c < 8; ++c) co[r][c] *= scale;
            *(float4*)&Ps[(w * 4 + r) * 68 + u * 4] =
                make_float4(s[r][0], s[r][1], s[r][2], s[r][3]);
        }
        __syncthreads();

        // O += P V
#pragma unroll 4
        for (int j = 0; j < 64; ++j) {
            float4 v0 = *(const float4*)&Vs[j * 128 + u * 8];
            float4 v1 = *(const float4*)&Vs[j * 128 + u * 8 + 4];
            float va[8] = {v0.x, v0.y, v0.z, v0.w, v1.x, v1.y, v1.z, v1.w};
#pragma unroll
            for (int r = 0; r < 4; ++r) {
                float pr = Ps[(w * 4 + r) * 68 + j];
#pragma unroll
                for (int c = 0; c < 8; ++c) co[r][c] += pr * va[c];
            }
        }
    }

    // Epilogue: normalize and write z[b*p][h*e]
    const int b = bh >> 4, h = bh & 15;
#pragma unroll
    for (int r = 0; r < 4; ++r) {
        float inv = 1.0f / l_i[r];
        int qi = q0 + w * 4 + r;
        float* o = g_z + (size_t)(b * SEQ + qi) * DMODEL + h * DHEAD + u * 8;
        float4 o0 = make_float4(co[r][0] * inv, co[r][1] * inv, co[r][2] * inv, co[r][3] * inv);
        float4 o1 = make_float4(co[r][4] * inv, co[r][5] * inv, co[r][6] * inv, co[r][7] * inv);
        *(float4*)o       = o0;
        *(float4*)(o + 4) = o1;
    }
}

// ---------------------------------------------------------------------------
extern "C" void kernel_launch(void* const* d_in, const int* in_sizes, int n_in,
                              void* d_out, int out_size) {
    (void)in_sizes; (void)n_in; (void)out_size;
    const float* qin = (const float*)d_in[0];
    const float* kin = (const float*)d_in[1];
    const float* vin = (const float*)d_in[2];
    const float* WQ  = (const float*)d_in[3];
    const float* WK  = (const float*)d_in[4];
    const float* WV  = (const float*)d_in[5];
    const float* WO  = (const float*)d_in[6];
    const float* bQ  = (const float*)d_in[7];
    const float* bK  = (const float*)d_in[8];
    const float* bV  = (const float*)d_in[9];
    const float* bO  = (const float*)d_in[10];
    float* out = (float*)d_out;

    float *pq, *pk, *pv, *pz;
    cudaGetSymbolAddress((void**)&pq, g_q);
    cudaGetSymbolAddress((void**)&pk, g_k);
    cudaGetSymbolAddress((void**)&pv, g_v);
    cudaGetSymbolAddress((void**)&pz, g_z);

    cudaFuncSetAttribute((const void*)flash_kernel,
                         cudaFuncAttributeMaxDynamicSharedMemorySize, FLASH_SMEM);

    rope_table_kernel<<<SEQ, 64>>>();

    dim3 ggrid(DMODEL / 128, MROWS / 128);
    gemm_kernel<<<ggrid, 256, GEMM_SMEM>>>(qin, WQ, DHEAD, bQ, pq, 0);
    gemm_kernel<<<ggrid, 256, GEMM_SMEM>>>(kin, WK, DHEAD, bK, pk, 0);
    gemm_kernel<<<ggrid, 256, GEMM_SMEM>>>(vin, WV, DHEAD, bV, pv, 0);

    rope_kernel<<<(BHN * SEQ * 64) / 256, 256>>>();

    flash_kernel<<<dim3(SEQ / 64, BHN), 256, FLASH_SMEM>>>();

    gemm_kernel<<<ggrid, 256, GEMM_SMEM>>>(pz, WO, DMODEL, bO, out, 1);
}

// round 3
// speedup vs baseline: 1.9701x; 1.9701x over previous
#include <cuda_runtime.h>
#include <cuda_bf16.h>
#include <math.h>
#include <stdint.h>

#define DMODEL 2048
#define NHEADS 16
#define DHEAD  128
#define SEQ    2048
#define BATCH  2
#define BHN    (BATCH*NHEADS)   // 32
#define MROWS  (BATCH*SEQ)      // 4096

// log2(e) / sqrt(128)
#define QSCALE (1.4426950408889634f * 0.08838834764831845f)

// ---- HMMA GEMM config: CTA 128x128, K-chunk 64, 8 warps (64x32 each) ----
#define PADK 72                       // bf16 elements per smem row (144 B)
#define TILE_BYTES (128 * PADK * 2)   // 18432
#define OFF_AH 0
#define OFF_AL (TILE_BYTES)
#define OFF_BH (2*TILE_BYTES)
#define OFF_BL (3*TILE_BYTES)
#define GEMM_SMEM (4*TILE_BYTES)      // 73728 B

#define FLASH_SMEM ((128*64 + 128*64 + 64*128 + 64*68) * 4)  // 115712 B

// ---------------- scratch (device globals; allocation-free) ----------------
__device__ float  g_q[(size_t)BHN * SEQ * DHEAD];
__device__ float  g_k[(size_t)BHN * SEQ * DHEAD];
__device__ float  g_v[(size_t)BHN * SEQ * DHEAD];
__device__ float  g_z[(size_t)MROWS * DMODEL];
__device__ float2 g_rope[SEQ * 64];

__device__ __nv_bfloat16 g_ah[(size_t)MROWS * DMODEL];
__device__ __nv_bfloat16 g_al[(size_t)MROWS * DMODEL];
__device__ __nv_bfloat16 g_wqh[(size_t)DMODEL * DMODEL];
__device__ __nv_bfloat16 g_wql[(size_t)DMODEL * DMODEL];
__device__ __nv_bfloat16 g_wkh[(size_t)DMODEL * DMODEL];
__device__ __nv_bfloat16 g_wkl[(size_t)DMODEL * DMODEL];
__device__ __nv_bfloat16 g_wvh[(size_t)DMODEL * DMODEL];
__device__ __nv_bfloat16 g_wvl[(size_t)DMODEL * DMODEL];
__device__ __nv_bfloat16 g_woh[(size_t)DMODEL * DMODEL];
__device__ __nv_bfloat16 g_wol[(size_t)DMODEL * DMODEL];

// ---------------- mma / ldmatrix helpers (sm_80+ PTX, compute_103-safe) ----
__device__ __forceinline__ void ldsm4(uint32_t* r, uint32_t addr) {
    asm volatile("ldmatrix.sync.aligned.m8n8.x4.shared.b16 {%0,%1,%2,%3}, [%4];"
                 : "=r"(r[0]), "=r"(r[1]), "=r"(r[2]), "=r"(r[3]) : "r"(addr));
}
__device__ __forceinline__ void mma16816(float* d, const uint32_t* a,
                                         uint32_t b0, uint32_t b1) {
    asm volatile(
        "mma.sync.aligned.m16n8k16.row.col.f32.bf16.bf16.f32 "
        "{%0,%1,%2,%3}, {%4,%5,%6,%7}, {%8,%9}, {%0,%1,%2,%3};"
        : "+f"(d[0]), "+f"(d[1]), "+f"(d[2]), "+f"(d[3])
        : "r"(a[0]), "r"(a[1]), "r"(a[2]), "r"(a[3]), "r"(b0), "r"(b1));
}

// ---------------------------------------------------------------------------
// RoPE table (fp32 angle, fp64 sin/cos)
// ---------------------------------------------------------------------------
__global__ void rope_table_kernel() {
    int p = blockIdx.x;
    int i = threadIdx.x;  // 0..63
    float freq = (float)pow(10000.0, (double)i / 64.0);
    float ang  = (float)p / freq;
    double s, c;
    sincos((double)ang, &s, &c);
    g_rope[p * 64 + i] = make_float2((float)s, (float)c);
}

// ---------------------------------------------------------------------------
// Apply rotary to q (QSCALE folded) and k, in place.
// ---------------------------------------------------------------------------
__global__ void rope_kernel() {
    int gid = blockIdx.x * 256 + threadIdx.x;
    int i    = gid & 63;
    int rest = gid >> 6;
    int p    = rest & 2047;
    int bh   = rest >> 11;
    float2 sc = g_rope[p * 64 + i];
    size_t base = ((size_t)bh * SEQ + p) * DHEAD;

    float x0 = g_q[base + i], x1 = g_q[base + 64 + i];
    g_q[base + i]      = (x0 * sc.y - x1 * sc.x) * QSCALE;
    g_q[base + 64 + i] = (x1 * sc.y + x0 * sc.x) * QSCALE;

    float y0 = g_k[base + i], y1 = g_k[base + 64 + i];
    g_k[base + i]      = y0 * sc.y - y1 * sc.x;
    g_k[base + 64 + i] = y1 * sc.y + y0 * sc.x;
}

// ---------------------------------------------------------------------------
// fp32 -> (bf16 hi, bf16 lo) split, elementwise.
// ---------------------------------------------------------------------------
__global__ void split_kernel(const float* __restrict__ x,
                             __nv_bfloat16* __restrict__ hi,
                             __nv_bfloat16* __restrict__ lo) {
    size_t i = ((size_t)blockIdx.x * 256 + threadIdx.x) * 4;
    float4 v = *(const float4*)(x + i);
    float a[4] = {v.x, v.y, v.z, v.w};
    uint32_t ph[2], pl[2];
#pragma unroll
    for (int j = 0; j < 2; ++j) {
        __nv_bfloat16 h0 = __float2bfloat16(a[2*j]);
        __nv_bfloat16 h1 = __float2bfloat16(a[2*j+1]);
        __nv_bfloat16 l0 = __float2bfloat16(a[2*j]   - __bfloat162float(h0));
        __nv_bfloat16 l1 = __float2bfloat16(a[2*j+1] - __bfloat162float(h1));
        ph[j] = (uint32_t)__bfloat16_as_ushort(h0) | ((uint32_t)__bfloat16_as_ushort(h1) << 16);
        pl[j] = (uint32_t)__bfloat16_as_ushort(l0) | ((uint32_t)__bfloat16_as_ushort(l1) << 16);
    }
    *(uint2*)((char*)hi + i * 2) = make_uint2(ph[0], ph[1]);
    *(uint2*)((char*)lo + i * 2) = make_uint2(pl[0], pl[1]);
}

// ---------------------------------------------------------------------------
// Transpose + split: src [H][R][C] fp32 -> dst[h*C + c][r] bf16 (hi, lo),
// dst row stride = R.
// ---------------------------------------------------------------------------
__global__ void transpose_split_kernel(const float* __restrict__ src,
                                       __nv_bfloat16* __restrict__ hi,
                                       __nv_bfloat16* __restrict__ lo,
                                       int R, int C) {
    __shared__ float t[32][33];
    int h  = blockIdx.z;
    int r0 = blockIdx.y << 5, c0 = blockIdx.x << 5;
    int tx = threadIdx.x, ty = threadIdx.y;  // 32 x 8
    const float* s = src + (size_t)h * R * C;
#pragma unroll
    for (int j = 0; j < 4; ++j)
        t[ty + 8 * j][tx] = s[(size_t)(r0 + ty + 8 * j) * C + c0 + tx];
    __syncthreads();
#pragma unroll
    for (int j = 0; j < 4; ++j) {
        int c = c0 + ty + 8 * j;
        float v = t[tx][ty + 8 * j];
        __nv_bfloat16 vh = __float2bfloat16(v);
        __nv_bfloat16 vl = __float2bfloat16(v - __bfloat162float(vh));
        size_t o = (size_t)(h * C + c) * R + r0 + tx;
        hi[o] = vh;
        lo[o] = vl;
    }
}

// ---------------------------------------------------------------------------
// HMMA (mma.sync bf16) split GEMM: out[4096, 2048] = A[4096,2048] * B^T + bias
// A pre-split hi/lo bf16 row-major [m][k]; B pre-split+transposed [n][k].
// 3 passes: Ah*Bh + Al*Bh + Ah*Bl, fp32 register accumulators.
// CTA 128x128, K-chunk 64, 8 warps in 2(m) x 4(n), warp tile 64x32.
// mode 0: out -> [b][h][p][e] (g_q/g_k/g_v); mode 1: row-major.
// ---------------------------------------------------------------------------
__global__ __launch_bounds__(256, 2) void gemm_hmma(
    const __nv_bfloat16* __restrict__ Ah,
    const __nv_bfloat16* __restrict__ Al,
    const __nv_bfloat16* __restrict__ Bh,
    const __nv_bfloat16* __restrict__ Bl,
    const float* __restrict__ bias,
    float* __restrict__ out,
    int mode)
{
    extern __shared__ char sm[];
    const uint32_t sb = (uint32_t)__cvta_generic_to_shared(sm);

    const int tid  = threadIdx.x;
    const int wid  = tid >> 5;
    const int lane = tid & 31;
    const int row0 = blockIdx.y * 128;
    const int n0   = blockIdx.x * 128;
    const int m_w  = (wid >> 2) * 64;   // 0 or 64
    const int n_w  = (wid & 3) * 32;    // 0,32,64,96

    // ldmatrix per-lane bases (byte offsets within a tile)
    const uint32_t aOff = (uint32_t)(lane & 15) * 144 + (uint32_t)((lane >> 4) << 3) * 2;
    const uint32_t bOff = (uint32_t)(((lane >> 4) << 3) + (lane & 7)) * 144 +
                          (uint32_t)(lane & 8) * 2;
    const uint32_t aBaseHi = sb + OFF_AH + aOff + m_w * 144;
    const uint32_t aBaseLo = sb + OFF_AL + aOff + m_w * 144;
    const uint32_t bBaseHi = sb + OFF_BH + bOff + n_w * 144;
    const uint32_t bBaseLo = sb + OFF_BL + bOff + n_w * 144;

    float acc[4][4][4];
#pragma unroll
    for (int i = 0; i < 4; ++i)
#pragma unroll
        for (int j = 0; j < 4; ++j)
#pragma unroll
            for (int r = 0; r < 4; ++r) acc[i][j][r] = 0.0f;

    // gmem load indices (per thread): 4 float4 per tile
    const int lr  = tid >> 3;          // 0..31 -> +32 per it
    const int lc8 = (tid & 7) * 8;     // 0..56

    for (int it = 0; it < DMODEL / 64; ++it) {
        const int k0 = it * 64;
        __syncthreads();
#pragma unroll
        for (int i = 0; i < 4; ++i) {
            int r = lr + i * 32;
            size_t ga = (size_t)(row0 + r) * DMODEL + k0 + lc8;
            size_t gb = (size_t)(n0 + r) * DMODEL + k0 + lc8;
            uint32_t so = (uint32_t)(r * 144 + lc8 * 2);
            *(float4*)(sm + OFF_AH + so) = *(const float4*)(Ah + ga);
            *(float4*)(sm + OFF_AL + so) = *(const float4*)(Al + ga);
            *(float4*)(sm + OFF_BH + so) = *(const float4*)(Bh + gb);
            *(float4*)(sm + OFF_BL + so) = *(const float4*)(Bl + gb);
        }
        __syncthreads();

#pragma unroll
        for (int kk = 0; kk < 4; ++kk) {
            uint32_t Af[4][4], Bf[2][4];
            // pass 1: Ah * Bh
#pragma unroll
            for (int mi = 0; mi < 4; ++mi)
                ldsm4(Af[mi], aBaseHi + mi * (16 * 144) + kk * 32);
#pragma unroll
            for (int ni = 0; ni < 2; ++ni)
                ldsm4(Bf[ni], bBaseHi + ni * (16 * 144) + kk * 32);
#pragma unroll
            for (int mi = 0; mi < 4; ++mi)
#pragma unroll
                for (int j = 0; j < 4; ++j)
                    mma16816(acc[mi][j], Af[mi], Bf[j >> 1][(j & 1) * 2],
                             Bf[j >> 1][(j & 1) * 2 + 1]);
            // pass 2: Al * Bh (reuse Bf)
            {
                uint32_t Al4[4];
#pragma unroll
                for (int mi = 0; mi < 4; ++mi) {
                    ldsm4(Al4, aBaseLo + mi * (16 * 144) + kk * 32);
#pragma unroll
                    for (int j = 0; j < 4; ++j)
                        mma16816(acc[mi][j], Al4, Bf[j >> 1][(j & 1) * 2],
                                 Bf[j >> 1][(j & 1) * 2 + 1]);
                }
            }
            // pass 3: Ah * Bl (reuse Af)
#pragma unroll
            for (int ni = 0; ni < 2; ++ni)
                ldsm4(Bf[ni], bBaseLo + ni * (16 * 144) + kk * 32);
#pragma unroll
            for (int mi = 0; mi < 4; ++mi)
#pragma unroll
                for (int j = 0; j < 4; ++j)
                    mma16816(acc[mi][j], Af[mi], Bf[j >> 1][(j & 1) * 2],
                             Bf[j >> 1][(j & 1) * 2 + 1]);
        }
    }

    // Epilogue: registers -> gmem (+bias)
    const int g = lane >> 2, t4 = lane & 3;
#pragma unroll
    for (int mi = 0; mi < 4; ++mi) {
        int m = row0 + m_w + mi * 16 + g;
#pragma unroll
        for (int j = 0; j < 4; ++j) {
            int col = n0 + n_w + j * 8 + t4 * 2;
            float b0 = bias[col], b1 = bias[col + 1];
            float2 v0 = make_float2(acc[mi][j][0] + b0, acc[mi][j][1] + b1);
            float2 v1 = make_float2(acc[mi][j][2] + b0, acc[mi][j][3] + b1);
            float *o0, *o1;
            if (mode == 0) {
                int h = col >> 7, e = col & 127;
                int b  = m >> 11, p = m & 2047;
                size_t base = (((size_t)(b * NHEADS + h) * SEQ) << 7) + e;
                o0 = out + base + ((size_t)p << 7);
                o1 = out + base + ((size_t)(p + 8) << 7);
            } else {
                o0 = out + (size_t)m * DMODEL + col;
                o1 = out + (size_t)(m + 8) * DMODEL + col;
            }
            *(float2*)o0 = v0;
            *(float2*)o1 = v1;
        }
    }
}

// ---------------------------------------------------------------------------
// Causal flash attention, fp32 (unchanged from passing R1 kernel).
// ---------------------------------------------------------------------------
__global__ __launch_bounds__(256, 1) void flash_kernel() {
    extern __shared__ float smf[];
    float* Qt = smf;              // [128][64]
    float* Kt = smf + 128 * 64;   // [128][64]
    float* Vs = Kt + 128 * 64;    // [64][128]
    float* Ps = Vs + 64 * 128;    // [64][68]

    const int tid = threadIdx.x;
    const int u = tid & 15;
    const int w = tid >> 4;
    const int bh = blockIdx.y;
    const int q0 = blockIdx.x * 64;

    const float* qp = g_q + (size_t)bh * SEQ * DHEAD;
    const float* kp = g_k + (size_t)bh * SEQ * DHEAD;
    const float* vp = g_v + (size_t)bh * SEQ * DHEAD;

#pragma unroll
    for (int it = 0; it < 8; ++it) {
        int f  = tid + it * 256;
        int j  = f >> 5;
        int d0 = (f & 31) * 4;
        float4 v = *(const float4*)(qp + (size_t)(q0 + j) * DHEAD + d0);
        Qt[(d0 + 0) * 64 + j] = v.x;
        Qt[(d0 + 1) * 64 + j] = v.y;
        Qt[(d0 + 2) * 64 + j] = v.z;
        Qt[(d0 + 3) * 64 + j] = v.w;
    }

    float m_i[4], l_i[4], co[4][8];
#pragma unroll
    for (int r = 0; r < 4; ++r) {
        m_i[r] = -1e30f; l_i[r] = 0.0f;
#pragma unroll
        for (int c = 0; c < 8; ++c) co[r][c] = 0.0f;
    }

    const int ntiles = blockIdx.x + 1;
    for (int t = 0; t < ntiles; ++t) {
        const int k0 = t * 64;
        __syncthreads();
#pragma unroll
        for (int it = 0; it < 8; ++it) {
            int f  = tid + it * 256;
            int j  = f >> 5;
            int d0 = (f & 31) * 4;
            float4 kv = *(const float4*)(kp + (size_t)(k0 + j) * DHEAD + d0);
            Kt[(d0 + 0) * 64 + j] = kv.x;
            Kt[(d0 + 1) * 64 + j] = kv.y;
            Kt[(d0 + 2) * 64 + j] = kv.z;
            Kt[(d0 + 3) * 64 + j] = kv.w;
            float4 vv = *(const float4*)(vp + (size_t)(k0 + j) * DHEAD + d0);
            *(float4*)&Vs[j * 128 + d0] = vv;
        }
        __syncthreads();

        float s[4][4];
#pragma unroll
        for (int r = 0; r < 4; ++r)
#pragma unroll
            for (int c = 0; c < 4; ++c) s[r][c] = 0.0f;

#pragma unroll 4
        for (int d = 0; d < 128; ++d) {
            float4 qv = *(const float4*)&Qt[d * 64 + w * 4];
            float4 kv = *(const float4*)&Kt[d * 64 + u * 4];
            float qa[4] = {qv.x, qv.y, qv.z, qv.w};
            float ka[4] = {kv.x, kv.y, kv.z, kv.w};
#pragma unroll
            for (int r = 0; r < 4; ++r)
#pragma unroll
                for (int c = 0; c < 4; ++c) s[r][c] += qa[r] * ka[c];
        }

        if (t == ntiles - 1) {
#pragma unroll
            for (int r = 0; r < 4; ++r)
#pragma unroll
                for (int c = 0; c < 4; ++c)
                    if (k0 + u * 4 + c > q0 + w * 4 + r) s[r][c] = -1e30f;
        }

#pragma unroll
        for (int r = 0; r < 4; ++r) {
            float mx = fmaxf(fmaxf(s[r][0], s[r][1]), fmaxf(s[r][2], s[r][3]));
#pragma unroll
            for (int off = 8; off >= 1; off >>= 1)
                mx = fmaxf(mx, __shfl_xor_sync(0xffffffffu, mx, off));
            float mn = fmaxf(m_i[r], mx);
            float scale = exp2f(m_i[r] - mn);
            float rs = 0.0f;
#pragma unroll
            for (int c = 0; c < 4; ++c) { s[r][c] = exp2f(s[r][c] - mn); rs += s[r][c]; }
#pragma unroll
            for (int off = 8; off >= 1; off >>= 1)
                rs += __shfl_xor_sync(0xffffffffu, rs, off);
            l_i[r] = l_i[r] * scale + rs;
            m_i[r] = mn;
#pragma unroll
            for (int c = 0; c < 8; ++c) co[r][c] *= scale;
            *(float4*)&Ps[(w * 4 + r) * 68 + u * 4] =
                make_float4(s[r][0], s[r][1], s[r][2], s[r][3]);
        }
        __syncthreads();

#pragma unroll 4
        for (int j = 0; j < 64; ++j) {
            float4 v0 = *(const float4*)&Vs[j * 128 + u * 8];
            float4 v1 = *(const float4*)&Vs[j * 128 + u * 8 + 4];
            float va[8] = {v0.x, v0.y, v0.z, v0.w, v1.x, v1.y, v1.z, v1.w};
#pragma unroll
            for (int r = 0; r < 4; ++r) {
                float pr = Ps[(w * 4 + r) * 68 + j];
#pragma unroll
                for (int c = 0; c < 8; ++c) co[r][c] += pr * va[c];
            }
        }
    }

    const int b = bh >> 4, h = bh & 15;
#pragma unroll
    for (int r = 0; r < 4; ++r) {
        float inv = 1.0f / l_i[r];
        int qi = q0 + w * 4 + r;
        float* o = g_z + (size_t)(b * SEQ + qi) * DMODEL + h * DHEAD + u * 8;
        float4 o0 = make_float4(co[r][0] * inv, co[r][1] * inv, co[r][2] * inv, co[r][3] * inv);
        float4 o1 = make_float4(co[r][4] * inv, co[r][5] * inv, co[r][6] * inv, co[r][7] * inv);
        *(float4*)o       = o0;
        *(float4*)(o + 4) = o1;
    }
}

// ---------------------------------------------------------------------------
extern "C" void kernel_launch(void* const* d_in, const int* in_sizes, int n_in,
                              void* d_out, int out_size) {
    (void)in_sizes; (void)n_in; (void)out_size;
    const float* qin = (const float*)d_in[0];
    const float* kin = (const float*)d_in[1];
    const float* vin = (const float*)d_in[2];
    const float* WQ  = (const float*)d_in[3];
    const float* WK  = (const float*)d_in[4];
    const float* WV  = (const float*)d_in[5];
    const float* WO  = (const float*)d_in[6];
    const float* bQ  = (const float*)d_in[7];
    const float* bK  = (const float*)d_in[8];
    const float* bV  = (const float*)d_in[9];
    const float* bO  = (const float*)d_in[10];
    float* out = (float*)d_out;

    float *pq, *pk, *pv, *pz;
    __nv_bfloat16 *ah, *al, *wqh, *wql, *wkh, *wkl, *wvh, *wvl, *woh, *wol;
    cudaGetSymbolAddress((void**)&pq, g_q);
    cudaGetSymbolAddress((void**)&pk, g_k);
    cudaGetSymbolAddress((void**)&pv, g_v);
    cudaGetSymbolAddress((void**)&pz, g_z);
    cudaGetSymbolAddress((void**)&ah, g_ah);
    cudaGetSymbolAddress((void**)&al, g_al);
    cudaGetSymbolAddress((void**)&wqh, g_wqh);
    cudaGetSymbolAddress((void**)&wql, g_wql);
    cudaGetSymbolAddress((void**)&wkh, g_wkh);
    cudaGetSymbolAddress((void**)&wkl, g_wkl);
    cudaGetSymbolAddress((void**)&wvh, g_wvh);
    cudaGetSymbolAddress((void**)&wvl, g_wvl);
    cudaGetSymbolAddress((void**)&woh, g_woh);
    cudaGetSymbolAddress((void**)&wol, g_wol);

    cudaFuncSetAttribute((const void*)flash_kernel,
                         cudaFuncAttributeMaxDynamicSharedMemorySize, FLASH_SMEM);
    cudaFuncSetAttribute((const void*)gemm_hmma,
                         cudaFuncAttributeMaxDynamicSharedMemorySize, GEMM_SMEM);

    rope_table_kernel<<<SEQ, 64>>>();

    // Weight transposes + splits (B^T [n][k] bf16 hi/lo)
    dim3 tb(32, 8);
    transpose_split_kernel<<<dim3(4, 64, 16), tb>>>(WQ, wqh, wql, DMODEL, DHEAD);
    transpose_split_kernel<<<dim3(4, 64, 16), tb>>>(WK, wkh, wkl, DMODEL, DHEAD);
    transpose_split_kernel<<<dim3(4, 64, 16), tb>>>(WV, wvh, wvl, DMODEL, DHEAD);
    transpose_split_kernel<<<dim3(64, 64, 1), tb>>>(WO, woh, wol, DMODEL, DMODEL);

    dim3 ggrid(DMODEL / 128, MROWS / 128);   // (16, 32)
    const int nsplit = (MROWS * DMODEL) / (256 * 4);

    split_kernel<<<nsplit, 256>>>(qin, ah, al);
    gemm_hmma<<<ggrid, 256, GEMM_SMEM>>>(ah, al, wqh, wql, bQ, pq, 0);
    split_kernel<<<nsplit, 256>>>(kin, ah, al);
    gemm_hmma<<<ggrid, 256, GEMM_SMEM>>>(ah, al, wkh, wkl, bK, pk, 0);
    split_kernel<<<nsplit, 256>>>(vin, ah, al);
    gemm_hmma<<<ggrid, 256, GEMM_SMEM>>>(ah, al, wvh, wvl, bV, pv, 0);

    rope_kernel<<<(BHN * SEQ * 64) / 256, 256>>>();

    flash_kernel<<<dim3(SEQ / 64, BHN), 256, FLASH_SMEM>>>();

    split_kernel<<<nsplit, 256>>>(pz, ah, al);
    gemm_hmma<<<ggrid, 256, GEMM_SMEM>>>(ah, al, woh, wol, bO, out, 1);
}

// round 4
// speedup vs baseline: 3.7439x; 1.9004x over previous
#include <cuda_runtime.h>
#include <cuda_bf16.h>
#include <math.h>
#include <stdint.h>

#define DMODEL 2048
#define NHEADS 16
#define DHEAD  128
#define SEQ    2048
#define BATCH  2
#define BHN    (BATCH*NHEADS)   // 32
#define MROWS  (BATCH*SEQ)      // 4096

// log2(e) / sqrt(128)
#define QSCALE (1.4426950408889634f * 0.08838834764831845f)

// ---- HMMA GEMM config: CTA 128x128, K-chunk 64, 8 warps (64x32 each) ----
#define PADK 72                       // bf16 elements per smem row (144 B)
#define TILE_BYTES (128 * PADK * 2)   // 18432
#define OFF_AH 0
#define OFF_AL (TILE_BYTES)
#define OFF_BH (2*TILE_BYTES)
#define OFF_BL (3*TILE_BYTES)
#define GEMM_SMEM (4*TILE_BYTES)      // 73728 B

// ---- HMMA flash config: 128 q x 128 kv, stride 272 B ----
#define FS   272                       // bytes per smem row (136 bf16)
#define FT   (128 * FS)                // 34816 per tile
#define FQH  0
#define FQL  (FT)
#define FKH  (2*FT)
#define FKL  (3*FT)
#define FVH  (4*FT)
#define FVL  (5*FT)
#define FLASH_SMEM (6*FT)              // 208896 B

// ---------------- scratch (device globals; allocation-free) ----------------
__device__ float  g_q[(size_t)BHN * SEQ * DHEAD];
__device__ float  g_k[(size_t)BHN * SEQ * DHEAD];
__device__ float  g_v[(size_t)BHN * SEQ * DHEAD];
__device__ float  g_z[(size_t)MROWS * DMODEL];
__device__ float2 g_rope[SEQ * 64];

__device__ __nv_bfloat16 g_ah[(size_t)MROWS * DMODEL];
__device__ __nv_bfloat16 g_al[(size_t)MROWS * DMODEL];
__device__ __nv_bfloat16 g_wqh[(size_t)DMODEL * DMODEL];
__device__ __nv_bfloat16 g_wql[(size_t)DMODEL * DMODEL];
__device__ __nv_bfloat16 g_wkh[(size_t)DMODEL * DMODEL];
__device__ __nv_bfloat16 g_wkl[(size_t)DMODEL * DMODEL];
__device__ __nv_bfloat16 g_wvh[(size_t)DMODEL * DMODEL];
__device__ __nv_bfloat16 g_wvl[(size_t)DMODEL * DMODEL];
__device__ __nv_bfloat16 g_woh[(size_t)DMODEL * DMODEL];
__device__ __nv_bfloat16 g_wol[(size_t)DMODEL * DMODEL];

__device__ __nv_bfloat16 g_qh[(size_t)BHN * SEQ * DHEAD];
__device__ __nv_bfloat16 g_ql[(size_t)BHN * SEQ * DHEAD];
__device__ __nv_bfloat16 g_kh[(size_t)BHN * SEQ * DHEAD];
__device__ __nv_bfloat16 g_kl[(size_t)BHN * SEQ * DHEAD];
__device__ __nv_bfloat16 g_vh[(size_t)BHN * SEQ * DHEAD];
__device__ __nv_bfloat16 g_vl[(size_t)BHN * SEQ * DHEAD];

// ---------------- mma / ldmatrix helpers ----------------
__device__ __forceinline__ void ldsm4(uint32_t* r, uint32_t addr) {
    asm volatile("ldmatrix.sync.aligned.m8n8.x4.shared.b16 {%0,%1,%2,%3}, [%4];"
                 : "=r"(r[0]), "=r"(r[1]), "=r"(r[2]), "=r"(r[3]) : "r"(addr));
}
__device__ __forceinline__ void ldsm4t(uint32_t* r, uint32_t addr) {
    asm volatile("ldmatrix.sync.aligned.m8n8.x4.trans.shared.b16 {%0,%1,%2,%3}, [%4];"
                 : "=r"(r[0]), "=r"(r[1]), "=r"(r[2]), "=r"(r[3]) : "r"(addr));
}
__device__ __forceinline__ void mma16816(float* d, const uint32_t* a,
                                         uint32_t b0, uint32_t b1) {
    asm volatile(
        "mma.sync.aligned.m16n8k16.row.col.f32.bf16.bf16.f32 "
        "{%0,%1,%2,%3}, {%4,%5,%6,%7}, {%8,%9}, {%0,%1,%2,%3};"
        : "+f"(d[0]), "+f"(d[1]), "+f"(d[2]), "+f"(d[3])
        : "r"(a[0]), "r"(a[1]), "r"(a[2]), "r"(a[3]), "r"(b0), "r"(b1));
}
__device__ __forceinline__ float ex2(float x) {
    float y; asm("ex2.approx.f32 %0, %1;" : "=f"(y) : "f"(x)); return y;
}
__device__ __forceinline__ uint32_t packbf(float lo, float hi) {
    uint32_t r; asm("cvt.rn.bf16x2.f32 %0, %1, %2;" : "=r"(r) : "f"(hi), "f"(lo));
    return r;
}

// ---------------------------------------------------------------------------
// RoPE table (fp32 angle, fp64 sin/cos)
// ---------------------------------------------------------------------------
__global__ void rope_table_kernel() {
    int p = blockIdx.x;
    int i = threadIdx.x;  // 0..63
    float freq = (float)pow(10000.0, (double)i / 64.0);
    float ang  = (float)p / freq;
    double s, c;
    sincos((double)ang, &s, &c);
    g_rope[p * 64 + i] = make_float2((float)s, (float)c);
}

// ---------------------------------------------------------------------------
// Rope + bf16 hi/lo split for q (QSCALE folded) and k.
// ---------------------------------------------------------------------------
__global__ void rope_split_kernel() {
    int gid = blockIdx.x * 256 + threadIdx.x;
    int i    = gid & 63;
    int rest = gid >> 6;
    int p    = rest & 2047;
    int bh   = rest >> 11;
    float2 sc = g_rope[p * 64 + i];
    size_t base = ((size_t)bh * SEQ + p) * DHEAD;

    float x0 = g_q[base + i], x1 = g_q[base + 64 + i];
    float q0 = (x0 * sc.y - x1 * sc.x) * QSCALE;
    float q1 = (x1 * sc.y + x0 * sc.x) * QSCALE;
    float y0 = g_k[base + i], y1 = g_k[base + 64 + i];
    float k0 = y0 * sc.y - y1 * sc.x;
    float k1 = y1 * sc.y + y0 * sc.x;

    __nv_bfloat16 h;
    h = __float2bfloat16(q0); g_qh[base + i]      = h; g_ql[base + i]      = __float2bfloat16(q0 - __bfloat162float(h));
    h = __float2bfloat16(q1); g_qh[base + 64 + i] = h; g_ql[base + 64 + i] = __float2bfloat16(q1 - __bfloat162float(h));
    h = __float2bfloat16(k0); g_kh[base + i]      = h; g_kl[base + i]      = __float2bfloat16(k0 - __bfloat162float(h));
    h = __float2bfloat16(k1); g_kh[base + 64 + i] = h; g_kl[base + 64 + i] = __float2bfloat16(k1 - __bfloat162float(h));
}

// ---------------------------------------------------------------------------
// fp32 -> (bf16 hi, bf16 lo) split, elementwise.
// ---------------------------------------------------------------------------
__global__ void split_kernel(const float* __restrict__ x,
                             __nv_bfloat16* __restrict__ hi,
                             __nv_bfloat16* __restrict__ lo) {
    size_t i = ((size_t)blockIdx.x * 256 + threadIdx.x) * 4;
    float4 v = *(const float4*)(x + i);
    float a[4] = {v.x, v.y, v.z, v.w};
    uint32_t ph[2], pl[2];
#pragma unroll
    for (int j = 0; j < 2; ++j) {
        __nv_bfloat16 h0 = __float2bfloat16(a[2*j]);
        __nv_bfloat16 h1 = __float2bfloat16(a[2*j+1]);
        __nv_bfloat16 l0 = __float2bfloat16(a[2*j]   - __bfloat162float(h0));
        __nv_bfloat16 l1 = __float2bfloat16(a[2*j+1] - __bfloat162float(h1));
        ph[j] = (uint32_t)__bfloat16_as_ushort(h0) | ((uint32_t)__bfloat16_as_ushort(h1) << 16);
        pl[j] = (uint32_t)__bfloat16_as_ushort(l0) | ((uint32_t)__bfloat16_as_ushort(l1) << 16);
    }
    *(uint2*)((char*)hi + i * 2) = make_uint2(ph[0], ph[1]);
    *(uint2*)((char*)lo + i * 2) = make_uint2(pl[0], pl[1]);
}

// ---------------------------------------------------------------------------
// Transpose + split: src [H][R][C] fp32 -> dst[h*C + c][r] bf16 (hi, lo).
// ---------------------------------------------------------------------------
__global__ void transpose_split_kernel(const float* __restrict__ src,
                                       __nv_bfloat16* __restrict__ hi,
                                       __nv_bfloat16* __restrict__ lo,
                                       int R, int C) {
    __shared__ float t[32][33];
    int h  = blockIdx.z;
    int r0 = blockIdx.y << 5, c0 = blockIdx.x << 5;
    int tx = threadIdx.x, ty = threadIdx.y;  // 32 x 8
    const float* s = src + (size_t)h * R * C;
#pragma unroll
    for (int j = 0; j < 4; ++j)
        t[ty + 8 * j][tx] = s[(size_t)(r0 + ty + 8 * j) * C + c0 + tx];
    __syncthreads();
#pragma unroll
    for (int j = 0; j < 4; ++j) {
        int c = c0 + ty + 8 * j;
        float v = t[tx][ty + 8 * j];
        __nv_bfloat16 vh = __float2bfloat16(v);
        __nv_bfloat16 vl = __float2bfloat16(v - __bfloat162float(vh));
        size_t o = (size_t)(h * C + c) * R + r0 + tx;
        hi[o] = vh;
        lo[o] = vl;
    }
}

// ---------------------------------------------------------------------------
// HMMA split GEMM (unchanged from R3): out = A * B^T + bias.
// ---------------------------------------------------------------------------
__global__ __launch_bounds__(256, 2) void gemm_hmma(
    const __nv_bfloat16* __restrict__ Ah,
    const __nv_bfloat16* __restrict__ Al,
    const __nv_bfloat16* __restrict__ Bh,
    const __nv_bfloat16* __restrict__ Bl,
    const float* __restrict__ bias,
    float* __restrict__ out,
    int mode)
{
    extern __shared__ char sm[];
    const uint32_t sb = (uint32_t)__cvta_generic_to_shared(sm);

    const int tid  = threadIdx.x;
    const int wid  = tid >> 5;
    const int lane = tid & 31;
    const int row0 = blockIdx.y * 128;
    const int n0   = blockIdx.x * 128;
    const int m_w  = (wid >> 2) * 64;
    const int n_w  = (wid & 3) * 32;

    const uint32_t aOff = (uint32_t)(lane & 15) * 144 + (uint32_t)((lane >> 4) << 3) * 2;
    const uint32_t bOff = (uint32_t)(((lane >> 4) << 3) + (lane & 7)) * 144 +
                          (uint32_t)(lane & 8) * 2;
    const uint32_t aBaseHi = sb + OFF_AH + aOff + m_w * 144;
    const uint32_t aBaseLo = sb + OFF_AL + aOff + m_w * 144;
    const uint32_t bBaseHi = sb + OFF_BH + bOff + n_w * 144;
    const uint32_t bBaseLo = sb + OFF_BL + bOff + n_w * 144;

    float acc[4][4][4];
#pragma unroll
    for (int i = 0; i < 4; ++i)
#pragma unroll
        for (int j = 0; j < 4; ++j)
#pragma unroll
            for (int r = 0; r < 4; ++r) acc[i][j][r] = 0.0f;

    const int lr  = tid >> 3;
    const int lc8 = (tid & 7) * 8;

    for (int it = 0; it < DMODEL / 64; ++it) {
        const int k0 = it * 64;
        __syncthreads();
#pragma unroll
        for (int i = 0; i < 4; ++i) {
            int r = lr + i * 32;
            size_t ga = (size_t)(row0 + r) * DMODEL + k0 + lc8;
            size_t gb = (size_t)(n0 + r) * DMODEL + k0 + lc8;
            uint32_t so = (uint32_t)(r * 144 + lc8 * 2);
            *(float4*)(sm + OFF_AH + so) = *(const float4*)(Ah + ga);
            *(float4*)(sm + OFF_AL + so) = *(const float4*)(Al + ga);
            *(float4*)(sm + OFF_BH + so) = *(const float4*)(Bh + gb);
            *(float4*)(sm + OFF_BL + so) = *(const float4*)(Bl + gb);
        }
        __syncthreads();

#pragma unroll
        for (int kk = 0; kk < 4; ++kk) {
            uint32_t Af[4][4], Bf[2][4];
#pragma unroll
            for (int mi = 0; mi < 4; ++mi)
                ldsm4(Af[mi], aBaseHi + mi * (16 * 144) + kk * 32);
#pragma unroll
            for (int ni = 0; ni < 2; ++ni)
                ldsm4(Bf[ni], bBaseHi + ni * (16 * 144) + kk * 32);
#pragma unroll
            for (int mi = 0; mi < 4; ++mi)
#pragma unroll
                for (int j = 0; j < 4; ++j)
                    mma16816(acc[mi][j], Af[mi], Bf[j >> 1][(j & 1) * 2],
                             Bf[j >> 1][(j & 1) * 2 + 1]);
            {
                uint32_t Al4[4];
#pragma unroll
                for (int mi = 0; mi < 4; ++mi) {
                    ldsm4(Al4, aBaseLo + mi * (16 * 144) + kk * 32);
#pragma unroll
                    for (int j = 0; j < 4; ++j)
                        mma16816(acc[mi][j], Al4, Bf[j >> 1][(j & 1) * 2],
                                 Bf[j >> 1][(j & 1) * 2 + 1]);
                }
            }
#pragma unroll
            for (int ni = 0; ni < 2; ++ni)
                ldsm4(Bf[ni], bBaseLo + ni * (16 * 144) + kk * 32);
#pragma unroll
            for (int mi = 0; mi < 4; ++mi)
#pragma unroll
                for (int j = 0; j < 4; ++j)
                    mma16816(acc[mi][j], Af[mi], Bf[j >> 1][(j & 1) * 2],
                             Bf[j >> 1][(j & 1) * 2 + 1]);
        }
    }

    const int g = lane >> 2, t4 = lane & 3;
#pragma unroll
    for (int mi = 0; mi < 4; ++mi) {
        int m = row0 + m_w + mi * 16 + g;
#pragma unroll
        for (int j = 0; j < 4; ++j) {
            int col = n0 + n_w + j * 8 + t4 * 2;
            float b0 = bias[col], b1 = bias[col + 1];
            float2 v0 = make_float2(acc[mi][j][0] + b0, acc[mi][j][1] + b1);
            float2 v1 = make_float2(acc[mi][j][2] + b0, acc[mi][j][3] + b1);
            float *o0, *o1;
            if (mode == 0) {
                int h = col >> 7, e = col & 127;
                int b  = m >> 11, p = m & 2047;
                size_t base = (((size_t)(b * NHEADS + h) * SEQ) << 7) + e;
                o0 = out + base + ((size_t)p << 7);
                o1 = out + base + ((size_t)(p + 8) << 7);
            } else {
                o0 = out + (size_t)m * DMODEL + col;
                o1 = out + (size_t)(m + 8) * DMODEL + col;
            }
            *(float2*)o0 = v0;
            *(float2*)o1 = v1;
        }
    }
}

// ---------------------------------------------------------------------------
// HMMA causal flash attention. CTA = 128 q-rows x 128 kv, 8 warps x 16 rows.
// S = Qh*Kh + Ql*Kh + Qh*Kl; O += Ph*Vh + Pl*Vh + Ph*Vl (P = hi+lo exact).
// Softmax in registers (exp2 domain, QSCALE pre-folded into q).
// ---------------------------------------------------------------------------
__global__ __launch_bounds__(256, 1) void flash_hmma() {
    extern __shared__ char sm[];
    const uint32_t sb = (uint32_t)__cvta_generic_to_shared(sm);

    const int tid  = threadIdx.x;
    const int wid  = tid >> 5;
    const int lane = tid & 31;
    const int bh   = blockIdx.y;
    const int qt   = gridDim.x - 1 - blockIdx.x;   // heavy tiles first
    const int q0   = qt * 128;

    const __nv_bfloat16* qh = g_qh + (size_t)bh * SEQ * DHEAD;
    const __nv_bfloat16* ql = g_ql + (size_t)bh * SEQ * DHEAD;
    const __nv_bfloat16* kh = g_kh + (size_t)bh * SEQ * DHEAD;
    const __nv_bfloat16* kl = g_kl + (size_t)bh * SEQ * DHEAD;
    const __nv_bfloat16* vh = g_vh + (size_t)bh * SEQ * DHEAD;
    const __nv_bfloat16* vl = g_vl + (size_t)bh * SEQ * DHEAD;

    // Load Q hi/lo tiles
#pragma unroll
    for (int i = 0; i < 8; ++i) {
        int f = tid + i * 256;
        int r = f >> 4, c8 = (f & 15) * 8;
        uint32_t off = (uint32_t)(r * FS + c8 * 2);
        size_t g = (size_t)(q0 + r) * DHEAD + c8;
        *(uint4*)(sm + FQH + off) = *(const uint4*)(qh + g);
        *(uint4*)(sm + FQL + off) = *(const uint4*)(ql + g);
    }

    // Fragment base addresses
    const uint32_t aOff = (uint32_t)(wid * 16 + (lane & 15)) * FS + ((lane >> 4) << 4);
    const uint32_t aQh = sb + FQH + aOff;
    const uint32_t aQl = sb + FQL + aOff;
    const uint32_t bOff = (uint32_t)(((lane >> 4) << 3) + (lane & 7)) * FS +
                          (uint32_t)((lane & 8) << 1);
    const uint32_t bKh = sb + FKH + bOff;
    const uint32_t bKl = sb + FKL + bOff;
    const uint32_t vOff = (uint32_t)(lane & 15) * FS + ((lane >> 4) << 4);
    const uint32_t bVh = sb + FVH + vOff;
    const uint32_t bVl = sb + FVL + vOff;

    float o[16][4];
#pragma unroll
    for (int j = 0; j < 16; ++j)
#pragma unroll
        for (int r = 0; r < 4; ++r) o[j][r] = 0.0f;
    float m1 = -1e30f, m2 = -1e30f, l1 = 0.0f, l2 = 0.0f;

    for (int t = 0; t <= qt; ++t) {
        const int k0 = t * 128;
        __syncthreads();
#pragma unroll
        for (int i = 0; i < 8; ++i) {
            int f = tid + i * 256;
            int r = f >> 4, c8 = (f & 15) * 8;
            uint32_t off = (uint32_t)(r * FS + c8 * 2);
            size_t g = (size_t)(k0 + r) * DHEAD + c8;
            *(uint4*)(sm + FKH + off) = *(const uint4*)(kh + g);
            *(uint4*)(sm + FKL + off) = *(const uint4*)(kl + g);
            *(uint4*)(sm + FVH + off) = *(const uint4*)(vh + g);
            *(uint4*)(sm + FVL + off) = *(const uint4*)(vl + g);
        }
        __syncthreads();

        // S = Q K^T (3 passes)
        float s[16][4];
#pragma unroll
        for (int j = 0; j < 16; ++j)
#pragma unroll
            for (int r = 0; r < 4; ++r) s[j][r] = 0.0f;

#pragma unroll
        for (int kk = 0; kk < 8; ++kk) {
            uint32_t qa[4], qb[4], kb[4];
            ldsm4(qa, aQh + kk * 32);
            ldsm4(qb, aQl + kk * 32);
#pragma unroll
            for (int nn = 0; nn < 8; ++nn) {
                ldsm4(kb, bKh + nn * (16 * FS) + kk * 32);
                mma16816(s[2*nn],   qa, kb[0], kb[1]);
                mma16816(s[2*nn+1], qa, kb[2], kb[3]);
                mma16816(s[2*nn],   qb, kb[0], kb[1]);
                mma16816(s[2*nn+1], qb, kb[2], kb[3]);
                ldsm4(kb, bKl + nn * (16 * FS) + kk * 32);
                mma16816(s[2*nn],   qa, kb[0], kb[1]);
                mma16816(s[2*nn+1], qa, kb[2], kb[3]);
            }
        }

        const int r1 = q0 + wid * 16 + (lane >> 2);
        const int r2 = r1 + 8;
        if (t == qt) {  // diagonal tile: causal mask
            const int c0 = k0 + (lane & 3) * 2;
#pragma unroll
            for (int j = 0; j < 16; ++j) {
                int col = c0 + j * 8;
                if (col     > r1) s[j][0] = -1e30f;
                if (col + 1 > r1) s[j][1] = -1e30f;
                if (col     > r2) s[j][2] = -1e30f;
                if (col + 1 > r2) s[j][3] = -1e30f;
            }
        }

        // Online softmax (rows r1, r2), reduce over 4 lanes (xor 1, 2)
        float mx1 = -1e30f, mx2 = -1e30f;
#pragma unroll
        for (int j = 0; j < 16; ++j) {
            mx1 = fmaxf(mx1, fmaxf(s[j][0], s[j][1]));
            mx2 = fmaxf(mx2, fmaxf(s[j][2], s[j][3]));
        }
        mx1 = fmaxf(mx1, __shfl_xor_sync(0xffffffffu, mx1, 1));
        mx1 = fmaxf(mx1, __shfl_xor_sync(0xffffffffu, mx1, 2));
        mx2 = fmaxf(mx2, __shfl_xor_sync(0xffffffffu, mx2, 1));
        mx2 = fmaxf(mx2, __shfl_xor_sync(0xffffffffu, mx2, 2));
        float mn1 = fmaxf(m1, mx1), mn2 = fmaxf(m2, mx2);
        float sc1 = ex2(m1 - mn1), sc2 = ex2(m2 - mn2);
        float rs1 = 0.0f, rs2 = 0.0f;
#pragma unroll
        for (int j = 0; j < 16; ++j) {
            s[j][0] = ex2(s[j][0] - mn1);
            s[j][1] = ex2(s[j][1] - mn1);
            s[j][2] = ex2(s[j][2] - mn2);
            s[j][3] = ex2(s[j][3] - mn2);
            rs1 += s[j][0] + s[j][1];
            rs2 += s[j][2] + s[j][3];
        }
        rs1 += __shfl_xor_sync(0xffffffffu, rs1, 1);
        rs1 += __shfl_xor_sync(0xffffffffu, rs1, 2);
        rs2 += __shfl_xor_sync(0xffffffffu, rs2, 1);
        rs2 += __shfl_xor_sync(0xffffffffu, rs2, 2);
        l1 = l1 * sc1 + rs1;  m1 = mn1;
        l2 = l2 * sc2 + rs2;  m2 = mn2;
#pragma unroll
        for (int j = 0; j < 16; ++j) {
            o[j][0] *= sc1; o[j][1] *= sc1;
            o[j][2] *= sc2; o[j][3] *= sc2;
        }

        // O += P V (3 passes), P fragments straight from S registers
#pragma unroll
        for (int kk = 0; kk < 8; ++kk) {
            uint32_t ph[4], pl[4], vb[4];
#pragma unroll
            for (int hv = 0; hv < 2; ++hv) {
                const float* sp = s[2*kk + hv];
                uint32_t p0 = packbf(sp[0], sp[1]);
                uint32_t p1 = packbf(sp[2], sp[3]);
                ph[hv*2]   = p0;
                ph[hv*2+1] = p1;
                pl[hv*2]   = packbf(sp[0] - __uint_as_float(p0 << 16),
                                    sp[1] - __uint_as_float(p0 & 0xffff0000u));
                pl[hv*2+1] = packbf(sp[2] - __uint_as_float(p1 << 16),
                                    sp[3] - __uint_as_float(p1 & 0xffff0000u));
            }
            // a-frag order: {k0-7 row g, k0-7 row g+8, k8-15 row g, k8-15 row g+8}
            uint32_t pha[4] = {ph[0], ph[1], ph[2], ph[3]};
            uint32_t pla[4] = {pl[0], pl[1], pl[2], pl[3]};
#pragma unroll
            for (int nn = 0; nn < 8; ++nn) {
                ldsm4t(vb, bVh + kk * (16 * FS) + nn * 32);
                mma16816(o[2*nn],   pha, vb[0], vb[1]);
                mma16816(o[2*nn+1], pha, vb[2], vb[3]);
                mma16816(o[2*nn],   pla, vb[0], vb[1]);
                mma16816(o[2*nn+1], pla, vb[2], vb[3]);
                ldsm4t(vb, bVl + kk * (16 * FS) + nn * 32);
                mma16816(o[2*nn],   pha, vb[0], vb[1]);
                mma16816(o[2*nn+1], pha, vb[2], vb[3]);
            }
        }
    }

    // Epilogue: normalize and write z[b*p][h*e]
    const int b = bh >> 4, h = bh & 15;
    const int r1 = q0 + wid * 16 + (lane >> 2);
    const float inv1 = 1.0f / l1, inv2 = 1.0f / l2;
    float* z1 = g_z + (size_t)(b * SEQ + r1) * DMODEL + h * DHEAD + (lane & 3) * 2;
    float* z2 = z1 + (size_t)8 * DMODEL;
#pragma unroll
    for (int j = 0; j < 16; ++j) {
        *(float2*)(z1 + j * 8) = make_float2(o[j][0] * inv1, o[j][1] * inv1);
        *(float2*)(z2 + j * 8) = make_float2(o[j][2] * inv2, o[j][3] * inv2);
    }
}

// ---------------------------------------------------------------------------
extern "C" void kernel_launch(void* const* d_in, const int* in_sizes, int n_in,
                              void* d_out, int out_size) {
    (void)in_sizes; (void)n_in; (void)out_size;
    const float* qin = (const float*)d_in[0];
    const float* kin = (const float*)d_in[1];
    const float* vin = (const float*)d_in[2];
    const float* WQ  = (const float*)d_in[3];
    const float* WK  = (const float*)d_in[4];
    const float* WV  = (const float*)d_in[5];
    const float* WO  = (const float*)d_in[6];
    const float* bQ  = (const float*)d_in[7];
    const float* bK  = (const float*)d_in[8];
    const float* bV  = (const float*)d_in[9];
    const float* bO  = (const float*)d_in[10];
    float* out = (float*)d_out;

    float *pq, *pk, *pv, *pz;
    __nv_bfloat16 *ah, *al, *wqh, *wql, *wkh, *wkl, *wvh, *wvl, *woh, *wol, *vh, *vl;
    cudaGetSymbolAddress((void**)&pq, g_q);
    cudaGetSymbolAddress((void**)&pk, g_k);
    cudaGetSymbolAddress((void**)&pv, g_v);
    cudaGetSymbolAddress((void**)&pz, g_z);
    cudaGetSymbolAddress((void**)&ah, g_ah);
    cudaGetSymbolAddress((void**)&al, g_al);
    cudaGetSymbolAddress((void**)&wqh, g_wqh);
    cudaGetSymbolAddress((void**)&wql, g_wql);
    cudaGetSymbolAddress((void**)&wkh, g_wkh);
    cudaGetSymbolAddress((void**)&wkl, g_wkl);
    cudaGetSymbolAddress((void**)&wvh, g_wvh);
    cudaGetSymbolAddress((void**)&wvl, g_wvl);
    cudaGetSymbolAddress((void**)&woh, g_woh);
    cudaGetSymbolAddress((void**)&wol, g_wol);
    cudaGetSymbolAddress((void**)&vh, g_vh);
    cudaGetSymbolAddress((void**)&vl, g_vl);

    cudaFuncSetAttribute((const void*)gemm_hmma,
                         cudaFuncAttributeMaxDynamicSharedMemorySize, GEMM_SMEM);
    cudaFuncSetAttribute((const void*)flash_hmma,
                         cudaFuncAttributeMaxDynamicSharedMemorySize, FLASH_SMEM);

    rope_table_kernel<<<SEQ, 64>>>();

    dim3 tb(32, 8);
    transpose_split_kernel<<<dim3(4, 64, 16), tb>>>(WQ, wqh, wql, DMODEL, DHEAD);
    transpose_split_kernel<<<dim3(4, 64, 16), tb>>>(WK, wkh, wkl, DMODEL, DHEAD);
    transpose_split_kernel<<<dim3(4, 64, 16), tb>>>(WV, wvh, wvl, DMODEL, DHEAD);
    transpose_split_kernel<<<dim3(64, 64, 1), tb>>>(WO, woh, wol, DMODEL, DMODEL);

    dim3 ggrid(DMODEL / 128, MROWS / 128);
    const int nsplit = (MROWS * DMODEL) / (256 * 4);

    split_kernel<<<nsplit, 256>>>(qin, ah, al);
    gemm_hmma<<<ggrid, 256, GEMM_SMEM>>>(ah, al, wqh, wql, bQ, pq, 0);
    split_kernel<<<nsplit, 256>>>(kin, ah, al);
    gemm_hmma<<<ggrid, 256, GEMM_SMEM>>>(ah, al, wkh, wkl, bK, pk, 0);
    split_kernel<<<nsplit, 256>>>(vin, ah, al);
    gemm_hmma<<<ggrid, 256, GEMM_SMEM>>>(ah, al, wvh, wvl, bV, pv, 0);

    rope_split_kernel<<<(BHN * SEQ * 64) / 256, 256>>>();
    split_kernel<<<((size_t)BHN * SEQ * DHEAD) / (256 * 4), 256>>>(pv, vh, vl);

    flash_hmma<<<dim3(SEQ / 128, BHN), 256, FLASH_SMEM>>>();

    split_kernel<<<nsplit, 256>>>(pz, ah, al);
    gemm_hmma<<<ggrid, 256, GEMM_SMEM>>>(ah, al, woh, wol, bO, out, 1);
}